// round 15
// baseline (speedup 1.0000x reference)
#include <cuda_runtime.h>
#include <cuda_bf16.h>
#include <cstdint>

#define HIDDEN     128
#define OUT_EMB    256
#define NUM_LAYERS 3
#define NUM_EDGES  1000000
#define NUM_NODES  50000

// ---------------- scratch ----------------------------------------------------
__device__ float g_v[(size_t)NUM_NODES * HIDDEN];
__device__ int   g_idx_is64;
// pre-split weights: layer0 [256][128], layers1-3 [256][256]; hi + lo bf16
#define WTOT (256*128 + 3*256*256)   // 229376
__device__ __align__(16) __nv_bfloat16 g_wh[WTOT];
__device__ __align__(16) __nv_bfloat16 g_wl[WTOT];

// ---------------- small helpers ---------------------------------------------
__device__ __forceinline__ uint32_t smem_u32(const void* p) {
    uint32_t a;
    asm("{ .reg .u64 t; cvta.to.shared.u64 t, %1; cvt.u32.u64 %0, t; }"
        : "=r"(a) : "l"(p));
    return a;
}
__device__ __forceinline__ void bsplit(float x, float& h, float& l) {
    __nv_bfloat16 b = __float2bfloat16(x);
    h = __bfloat162float(b);
    l = x - h;
}
__device__ __forceinline__ uint32_t packbf2(float lo, float hi) {
    __nv_bfloat162 v = __halves2bfloat162(__float2bfloat16(lo), __float2bfloat16(hi));
    return *reinterpret_cast<uint32_t*>(&v);
}
__device__ __forceinline__ void ldsm4(uint32_t* r, uint32_t addr) {
    asm volatile("ldmatrix.sync.aligned.m8n8.x4.shared.b16 {%0,%1,%2,%3}, [%4];"
                 : "=r"(r[0]), "=r"(r[1]), "=r"(r[2]), "=r"(r[3]) : "r"(addr));
}
__device__ __forceinline__ void mma16816(float* d, const uint32_t* a, const uint32_t* b) {
    asm volatile("mma.sync.aligned.m16n8k16.row.col.f32.bf16.bf16.f32 "
                 "{%0,%1,%2,%3}, {%4,%5,%6,%7}, {%8,%9}, {%0,%1,%2,%3};"
                 : "+f"(d[0]), "+f"(d[1]), "+f"(d[2]), "+f"(d[3])
                 : "r"(a[0]), "r"(a[1]), "r"(a[2]), "r"(a[3]),
                   "r"(b[0]), "r"(b[1]));
}
__device__ __forceinline__ void cp16(uint32_t dst, const void* src) {
    asm volatile("cp.async.cg.shared.global [%0], [%1], 16;"
                 :: "r"(dst), "l"(src) : "memory");
}
#define CP_COMMIT() asm volatile("cp.async.commit_group;" ::: "memory")
#define CP_WAIT0()  asm volatile("cp.async.wait_group 0;"  ::: "memory")
__device__ __forceinline__ float silu(float x) { return x / (1.f + __expf(-x)); }

// ---------------- front kernels ----------------------------------------------
__global__ void detect_idx_kernel(const int* __restrict__ idx) {
    if (blockIdx.x == 0 && threadIdx.x == 0) {
        int z = 0;
        #pragma unroll
        for (int j = 1; j < 64; j += 2) z |= idx[j];
        g_idx_is64 = (z == 0) ? 1 : 0;
    }
}

__global__ void zero_v_kernel() {
    const int i  = blockIdx.x * blockDim.x + threadIdx.x;
    const int n4 = NUM_NODES * HIDDEN / 4;
    if (i < n4) reinterpret_cast<float4*>(g_v)[i] = make_float4(0.f, 0.f, 0.f, 0.f);
}

__global__ void presplit_kernel(const float* __restrict__ W_up,
                                const float* __restrict__ Ws) {
    const int i = blockIdx.x * blockDim.x + threadIdx.x;
    if (i >= WTOT) return;
    const float v = (i < 256 * 128) ? W_up[i] : Ws[i - 256 * 128];
    float h, l;
    bsplit(v, h, l);
    g_wh[i] = __float2bfloat16(h);
    g_wl[i] = __float2bfloat16(l);
}

__global__ void scatter_kernel(const float4* __restrict__ e2,
                               const void*   __restrict__ idx_raw) {
    const long long g = (long long)blockIdx.x * blockDim.x + threadIdx.x;
    if (g >= (long long)NUM_EDGES * 32) return;
    const int edge = (int)(g >> 5);
    const int lane = (int)(g & 31);
    int node;
    if (g_idx_is64) node = (int)reinterpret_cast<const long long*>(idx_raw)[edge];
    else            node = reinterpret_cast<const int*>(idx_raw)[edge];
    const float4 val = e2[(long long)edge * 32 + lane];
    float* dst = g_v + (size_t)node * HIDDEN + (size_t)lane * 4;
    asm volatile("red.global.add.v4.f32 [%0], {%1, %2, %3, %4};"
                 :: "l"(dst), "f"(val.x), "f"(val.y), "f"(val.z), "f"(val.w)
                 : "memory");
}

// ---------------- tensor-core MLP (512 threads, 16 warps, M=128) -------------
// Warp w: wm = w&3 -> rows wm*32..+31 ; wn = w>>2 -> cols wn*64..+63.
// Warp tile m32n64 (128 B ldsm per mma). B fragments consumed per-bp (8 live
// regs), next panel staged via cp.async (no register prefetch) -> no spills.
#define SM_A_HI  0
#define SM_A_LO  67584                      // 128*528
#define BROW     80
#define BMAT     20480                      // 256*80
#define BSLOT    40960                      // hi + lo
#define SM_B     135168
#define SM_BIAS  217088                     // 135168 + 2*40960
#define SM_WOUT  218112
#define SM_PART  219136                     // 128 rows x 4 n-blocks x f32 = 2 KB
#define SMEM_BYTES 221184

__global__ void __launch_bounds__(512, 1)
mlp_mma_kernel(const float* __restrict__ b_up, const float* __restrict__ bs,
               const float* __restrict__ W_out, float* __restrict__ out)
{
    extern __shared__ char smem[];
    const uint32_t sb = smem_u32(smem);
    const int t   = threadIdx.x;
    const int wid = t >> 5;
    const int lid = t & 31;
    const int wm  = wid & 3;       // m32 block (0..3)
    const int wn  = wid >> 2;      // n64 block (0..3)
    const int node0 = blockIdx.x * 128;

    // B-staging coordinates (shared by all panels)
    const int sn = t >> 1;          // row, 2 threads per row
    const int sc = t & 1;           // half-row (16 bf16)

    // ---- initial A: g_v rows -> bf16 hi/lo split into SMEM ----
    {
        const int m    = t >> 2;          // 0..127
        const int kc0  = (t & 3) * 32;    // 32 floats per thread
        const int node = node0 + m;
        float x[32];
        if (node < NUM_NODES) {
            const float4* src =
                reinterpret_cast<const float4*>(g_v + (size_t)node * HIDDEN + kc0);
            #pragma unroll
            for (int i = 0; i < 8; ++i) {
                const float4 v4 = src[i];
                x[4*i] = v4.x; x[4*i+1] = v4.y; x[4*i+2] = v4.z; x[4*i+3] = v4.w;
            }
        } else {
            #pragma unroll
            for (int i = 0; i < 32; ++i) x[i] = 0.f;
        }
        uint32_t hi[16], lo[16];
        #pragma unroll
        for (int j = 0; j < 16; ++j) {
            float h0, l0, h1, l1;
            bsplit(x[2*j], h0, l0);
            bsplit(x[2*j+1], h1, l1);
            hi[j] = packbf2(h0, h1);
            lo[j] = packbf2(l0, l1);
        }
        char* dh = smem + SM_A_HI + m * 528 + kc0 * 2;
        char* dl = smem + SM_A_LO + m * 528 + kc0 * 2;
        #pragma unroll
        for (int u = 0; u < 4; ++u) {
            *reinterpret_cast<uint4*>(dh + u * 16) =
                make_uint4(hi[4*u], hi[4*u+1], hi[4*u+2], hi[4*u+3]);
            *reinterpret_cast<uint4*>(dl + u * 16) =
                make_uint4(lo[4*u], lo[4*u+1], lo[4*u+2], lo[4*u+3]);
        }
    }

    float acc[2][8][4];

    for (int layer = 0; layer < 4; ++layer) {
        const int K    = (layer == 0) ? HIDDEN : OUT_EMB;
        const int npan = K / 32;
        const int Loff = (layer == 0) ? 0 : 256 * 128 + (layer - 1) * 256 * 256;

        // ---- per-layer constants + stage panel 0 via cp.async ----
        {
            if (t < 256) {
                reinterpret_cast<float*>(smem + SM_BIAS)[t] =
                    (layer == 0) ? b_up[t] : bs[(layer - 1) * OUT_EMB + t];
                if (layer == 3)
                    reinterpret_cast<float*>(smem + SM_WOUT)[t] = W_out[t];
            }
            const uint32_t dH = sb + SM_B + sn * BROW + sc * 32;
            const int src = Loff + sn * K + sc * 16;
            cp16(dH,              g_wh + src);
            cp16(dH + 16,         g_wh + src + 8);
            cp16(dH + BMAT,       g_wl + src);
            cp16(dH + BMAT + 16,  g_wl + src + 8);
            CP_COMMIT();
            CP_WAIT0();
        }
        __syncthreads();

        #pragma unroll
        for (int ma = 0; ma < 2; ++ma)
            #pragma unroll
            for (int na = 0; na < 8; ++na)
                #pragma unroll
                for (int i = 0; i < 4; ++i) acc[ma][na][i] = 0.f;

        for (int p = 0; p < npan; ++p) {
            const bool hasNext = (p + 1 < npan);
            if (hasNext) {   // stage next panel via cp.async (no regs held)
                const uint32_t dH = sb + SM_B + (uint32_t)((p + 1) & 1) * BSLOT
                                    + sn * BROW + sc * 32;
                const int src = Loff + sn * K + (p + 1) * 32 + sc * 16;
                cp16(dH,             g_wh + src);
                cp16(dH + 16,        g_wh + src + 8);
                cp16(dH + BMAT,      g_wl + src);
                cp16(dH + BMAT + 16, g_wl + src + 8);
                CP_COMMIT();
            }

            // ---- compute panel p (k = p*32 .. +31) ----
            const uint32_t bsH = sb + SM_B + (uint32_t)(p & 1) * BSLOT;
            #pragma unroll
            for (int ks = 0; ks < 2; ++ks) {
                const int kk = ks * 16;
                uint32_t Ah[2][4], Al[2][4];
                #pragma unroll
                for (int ma = 0; ma < 2; ++ma) {
                    const int row = wm * 32 + ma * 16 + (lid & 7) + ((lid >> 3) & 1) * 8;
                    const int kc  = p * 32 + kk + (lid >> 4) * 8;
                    const uint32_t ad = sb + SM_A_HI + row * 528 + kc * 2;
                    ldsm4(Ah[ma], ad);
                    ldsm4(Al[ma], ad + SM_A_LO);
                }
                // B fragments: one bp (2 n-atoms) at a time -> 8 live regs
                #pragma unroll
                for (int bp = 0; bp < 4; ++bp) {
                    const int n  = wn * 64 + bp * 16 + (lid & 7) + (lid >> 4) * 8;
                    const int kb = kk + ((lid >> 3) & 1) * 8;
                    const uint32_t ad = bsH + n * BROW + kb * 2;
                    uint32_t bh[4], bl[4];
                    ldsm4(bh, ad);
                    ldsm4(bl, ad + BMAT);
                    #pragma unroll
                    for (int ma = 0; ma < 2; ++ma) {
                        mma16816(acc[ma][2*bp],     Ah[ma], bh);
                        mma16816(acc[ma][2*bp],     Ah[ma], bl);
                        mma16816(acc[ma][2*bp],     Al[ma], bh);
                        mma16816(acc[ma][2*bp + 1], Ah[ma], bh + 2);
                        mma16816(acc[ma][2*bp + 1], Ah[ma], bl + 2);
                        mma16816(acc[ma][2*bp + 1], Al[ma], bh + 2);
                    }
                }
            }

            if (hasNext) CP_WAIT0();
            __syncthreads();
        }

        // ---- epilogue ----
        const float* bias_s = reinterpret_cast<const float*>(smem + SM_BIAS);
        if (layer < 3) {
            #pragma unroll
            for (int ma = 0; ma < 2; ++ma)
                #pragma unroll
                for (int na = 0; na < 8; ++na) {
                    const int col = wn * 64 + na * 8 + (lid & 3) * 2;
                    const int r0  = wm * 32 + ma * 16 + (lid >> 2);
                    const float bv0 = bias_s[col], bv1 = bias_s[col + 1];
                    float x0 = acc[ma][na][0] + bv0;
                    float x1 = acc[ma][na][1] + bv1;
                    float x2 = acc[ma][na][2] + bv0;
                    float x3 = acc[ma][na][3] + bv1;
                    if (layer > 0) { x0 = silu(x0); x1 = silu(x1); x2 = silu(x2); x3 = silu(x3); }
                    float h0,l0,h1,l1,h2,l2,h3,l3;
                    bsplit(x0,h0,l0); bsplit(x1,h1,l1);
                    bsplit(x2,h2,l2); bsplit(x3,h3,l3);
                    *reinterpret_cast<uint32_t*>(smem + SM_A_HI + r0*528 + col*2) = packbf2(h0,h1);
                    *reinterpret_cast<uint32_t*>(smem + SM_A_LO + r0*528 + col*2) = packbf2(l0,l1);
                    *reinterpret_cast<uint32_t*>(smem + SM_A_HI + (r0+8)*528 + col*2) = packbf2(h2,h3);
                    *reinterpret_cast<uint32_t*>(smem + SM_A_LO + (r0+8)*528 + col*2) = packbf2(l2,l3);
                }
            __syncthreads();
        } else {
            const float* wo = reinterpret_cast<const float*>(smem + SM_WOUT);
            float* part = reinterpret_cast<float*>(smem + SM_PART);
            #pragma unroll
            for (int ma = 0; ma < 2; ++ma) {
                float p0 = 0.f, p1 = 0.f;
                #pragma unroll
                for (int na = 0; na < 8; ++na) {
                    const int col = wn * 64 + na * 8 + (lid & 3) * 2;
                    const float bv0 = bias_s[col], bv1 = bias_s[col + 1];
                    const float w0 = wo[col], w1 = wo[col + 1];
                    p0 = fmaf(silu(acc[ma][na][0] + bv0), w0, p0);
                    p0 = fmaf(silu(acc[ma][na][1] + bv1), w1, p0);
                    p1 = fmaf(silu(acc[ma][na][2] + bv0), w0, p1);
                    p1 = fmaf(silu(acc[ma][na][3] + bv1), w1, p1);
                }
                p0 += __shfl_xor_sync(0xffffffffu, p0, 1);
                p0 += __shfl_xor_sync(0xffffffffu, p0, 2);
                p1 += __shfl_xor_sync(0xffffffffu, p1, 1);
                p1 += __shfl_xor_sync(0xffffffffu, p1, 2);
                if ((lid & 3) == 0) {
                    const int r0 = wm * 32 + ma * 16 + (lid >> 2);
                    part[r0 * 4 + wn]       = p0;
                    part[(r0 + 8) * 4 + wn] = p1;
                }
            }
            __syncthreads();
            if (t < 128) {
                const int node = node0 + t;
                if (node < NUM_NODES)
                    out[node] = part[4*t] + part[4*t+1] + part[4*t+2] + part[4*t+3];
            }
        }
    }
}

// ---------------------------------------------------------------------------
extern "C" void kernel_launch(void* const* d_in, const int* in_sizes, int n_in,
                              void* d_out, int out_size)
{
    const float* e2    = (const float*)d_in[0];
    const void*  idx   = d_in[1];
    const float* W_up  = (const float*)d_in[2];
    const float* b_up  = (const float*)d_in[3];
    const float* Ws    = (const float*)d_in[4];
    const float* bs    = (const float*)d_in[5];
    const float* W_out = (const float*)d_in[6];
    float* out = (float*)d_out;

    cudaFuncSetAttribute(mlp_mma_kernel,
                         cudaFuncAttributeMaxDynamicSharedMemorySize, SMEM_BYTES);

    detect_idx_kernel<<<1, 1>>>((const int*)idx);
    presplit_kernel<<<(WTOT + 255) / 256, 256>>>(W_up, Ws);

    const int n4 = NUM_NODES * HIDDEN / 4;
    zero_v_kernel<<<(n4 + 255) / 256, 256>>>();

    const long long scatter_threads = (long long)NUM_EDGES * 32;
    scatter_kernel<<<(int)((scatter_threads + 255) / 256), 256>>>(
        (const float4*)e2, idx);

    const int mlp_blocks = (NUM_NODES + 127) / 128;   // 391
    mlp_mma_kernel<<<mlp_blocks, 512, SMEM_BYTES>>>(b_up, bs, W_out, out);
}

// round 16
// speedup vs baseline: 1.0468x; 1.0468x over previous
#include <cuda_runtime.h>
#include <cuda_bf16.h>
#include <cstdint>

#define HIDDEN     128
#define OUT_EMB    256
#define NUM_LAYERS 3
#define NUM_EDGES  1000000
#define NUM_NODES  50000

// ---------------- scratch ----------------------------------------------------
__device__ float g_v[(size_t)NUM_NODES * HIDDEN];
__device__ int   g_idx_is64;
// pre-split weights: layer0 [256][128], layers1-3 [256][256]; hi + lo bf16
#define WTOT (256*128 + 3*256*256)   // 229376
__device__ __align__(16) __nv_bfloat16 g_wh[WTOT];
__device__ __align__(16) __nv_bfloat16 g_wl[WTOT];

// ---------------- small helpers ---------------------------------------------
__device__ __forceinline__ uint32_t smem_u32(const void* p) {
    uint32_t a;
    asm("{ .reg .u64 t; cvta.to.shared.u64 t, %1; cvt.u32.u64 %0, t; }"
        : "=r"(a) : "l"(p));
    return a;
}
__device__ __forceinline__ void bsplit(float x, float& h, float& l) {
    __nv_bfloat16 b = __float2bfloat16(x);
    h = __bfloat162float(b);
    l = x - h;
}
__device__ __forceinline__ uint32_t packbf2(float lo, float hi) {
    __nv_bfloat162 v = __halves2bfloat162(__float2bfloat16(lo), __float2bfloat16(hi));
    return *reinterpret_cast<uint32_t*>(&v);
}
__device__ __forceinline__ void ldsm4(uint32_t* r, uint32_t addr) {
    asm volatile("ldmatrix.sync.aligned.m8n8.x4.shared.b16 {%0,%1,%2,%3}, [%4];"
                 : "=r"(r[0]), "=r"(r[1]), "=r"(r[2]), "=r"(r[3]) : "r"(addr));
}
__device__ __forceinline__ void mma16816(float* d, const uint32_t* a, const uint32_t* b) {
    asm volatile("mma.sync.aligned.m16n8k16.row.col.f32.bf16.bf16.f32 "
                 "{%0,%1,%2,%3}, {%4,%5,%6,%7}, {%8,%9}, {%0,%1,%2,%3};"
                 : "+f"(d[0]), "+f"(d[1]), "+f"(d[2]), "+f"(d[3])
                 : "r"(a[0]), "r"(a[1]), "r"(a[2]), "r"(a[3]),
                   "r"(b[0]), "r"(b[1]));
}
__device__ __forceinline__ void cp16(uint32_t dst, const void* src) {
    asm volatile("cp.async.cg.shared.global [%0], [%1], 16;"
                 :: "r"(dst), "l"(src) : "memory");
}
#define CP_COMMIT() asm volatile("cp.async.commit_group;" ::: "memory")
#define CP_WAIT0()  asm volatile("cp.async.wait_group 0;"  ::: "memory")
__device__ __forceinline__ float silu(float x) { return x / (1.f + __expf(-x)); }

// ---------------- fused front kernel -----------------------------------------
// blocks [0, 6250): zero g_v.   blocks [6250, 7146): presplit weights.
// block 0 / thread 0 additionally detects idx dtype.
#define Z_BLOCKS 6250
#define P_BLOCKS 896
__global__ void front_kernel(const int* __restrict__ idx,
                             const float* __restrict__ W_up,
                             const float* __restrict__ Ws) {
    const int b = blockIdx.x;
    if (b == 0 && threadIdx.x == 0) {
        int z = 0;
        #pragma unroll
        for (int j = 1; j < 64; j += 2) z |= idx[j];
        g_idx_is64 = (z == 0) ? 1 : 0;
    }
    if (b < Z_BLOCKS) {
        const int i = b * 256 + threadIdx.x;            // < 1.6M exactly
        reinterpret_cast<float4*>(g_v)[i] = make_float4(0.f, 0.f, 0.f, 0.f);
    } else {
        const int i = (b - Z_BLOCKS) * 256 + threadIdx.x;   // < WTOT exactly
        const float v = (i < 256 * 128) ? W_up[i] : Ws[i - 256 * 128];
        float h, l;
        bsplit(v, h, l);
        g_wh[i] = __float2bfloat16(h);
        g_wl[i] = __float2bfloat16(l);
    }
}

// ---------------- scatter -----------------------------------------------------
// __ldcs on the 512MB e2 stream (evict-first) keeps the 25.6MB g_v atomic
// working set L2-resident -> DRAM traffic drops to the pure-read floor.
__global__ void scatter_kernel(const float4* __restrict__ e2,
                               const void*   __restrict__ idx_raw) {
    const long long g = (long long)blockIdx.x * blockDim.x + threadIdx.x;
    if (g >= (long long)NUM_EDGES * 32) return;
    const int edge = (int)(g >> 5);
    const int lane = (int)(g & 31);
    int node;
    if (g_idx_is64) node = (int)reinterpret_cast<const long long*>(idx_raw)[edge];
    else            node = reinterpret_cast<const int*>(idx_raw)[edge];
    const float4 val = __ldcs(e2 + (long long)edge * 32 + lane);
    float* dst = g_v + (size_t)node * HIDDEN + (size_t)lane * 4;
    asm volatile("red.global.add.v4.f32 [%0], {%1, %2, %3, %4};"
                 :: "l"(dst), "f"(val.x), "f"(val.y), "f"(val.z), "f"(val.w)
                 : "memory");
}

// ---------------- tensor-core MLP (512 threads, 16 warps, M=128) -------------
// Warp tile m32n64. B panels cp.async double-buffered with CROSS-LAYER
// prefetch (next layer's panel 0 staged during this layer's last panel +
// epilogue). All biases + W_out hoisted into SMEM once.
#define SM_A_HI  0
#define SM_A_LO  67584                      // 128*528
#define BROW     80
#define BMAT     20480                      // 256*80
#define BSLOT    40960                      // hi + lo
#define SM_B     135168
#define SM_BIAS  217088                     // layer l bias at +l*1024; wout +4096
#define SM_PART  222208                     // 128 rows x 4 n-blocks x f32 = 2 KB
#define SMEM_BYTES 224256

__global__ void __launch_bounds__(512, 1)
mlp_mma_kernel(const float* __restrict__ b_up, const float* __restrict__ bs,
               const float* __restrict__ W_out, float* __restrict__ out)
{
    extern __shared__ char smem[];
    const uint32_t sb = smem_u32(smem);
    const int t   = threadIdx.x;
    const int wid = t >> 5;
    const int lid = t & 31;
    const int wm  = wid & 3;       // m32 block (0..3)
    const int wn  = wid >> 2;      // n64 block (0..3)
    const int node0 = blockIdx.x * 128;

    // B-staging coordinates (shared by all panels)
    const int sn = t >> 1;          // row, 2 threads per row
    const int sc = t & 1;           // half-row (16 bf16)
    const uint32_t stago = sn * BROW + sc * 32;   // dst offset within a slot
    const int      ssrc  = sn * 0 + sc * 16;      // (sn*K added per use)

    // ---- preamble: stage layer0/panel0 (cp.async, overlaps A-load) ----
    {
        const uint32_t dH = sb + SM_B + stago;
        const int src = sn * HIDDEN + sc * 16;
        cp16(dH,             g_wh + src);
        cp16(dH + 16,        g_wh + src + 8);
        cp16(dH + BMAT,      g_wl + src);
        cp16(dH + BMAT + 16, g_wl + src + 8);
        CP_COMMIT();
    }
    // ---- hoist all biases + W_out into SMEM ----
    if (t < 256) {
        float* bias_all = reinterpret_cast<float*>(smem + SM_BIAS);
        bias_all[t] = b_up[t];
        #pragma unroll
        for (int l = 1; l < 4; ++l)
            bias_all[l * 256 + t] = bs[(l - 1) * OUT_EMB + t];
        bias_all[4 * 256 + t] = W_out[t];
    }
    // ---- initial A: g_v rows -> bf16 hi/lo split into SMEM ----
    {
        const int m    = t >> 2;          // 0..127
        const int kc0  = (t & 3) * 32;    // 32 floats per thread
        const int node = node0 + m;
        float x[32];
        if (node < NUM_NODES) {
            const float4* src =
                reinterpret_cast<const float4*>(g_v + (size_t)node * HIDDEN + kc0);
            #pragma unroll
            for (int i = 0; i < 8; ++i) {
                const float4 v4 = src[i];
                x[4*i] = v4.x; x[4*i+1] = v4.y; x[4*i+2] = v4.z; x[4*i+3] = v4.w;
            }
        } else {
            #pragma unroll
            for (int i = 0; i < 32; ++i) x[i] = 0.f;
        }
        uint32_t hi[16], lo[16];
        #pragma unroll
        for (int j = 0; j < 16; ++j) {
            float h0, l0, h1, l1;
            bsplit(x[2*j], h0, l0);
            bsplit(x[2*j+1], h1, l1);
            hi[j] = packbf2(h0, h1);
            lo[j] = packbf2(l0, l1);
        }
        char* dh = smem + SM_A_HI + m * 528 + kc0 * 2;
        char* dl = smem + SM_A_LO + m * 528 + kc0 * 2;
        #pragma unroll
        for (int u = 0; u < 4; ++u) {
            *reinterpret_cast<uint4*>(dh + u * 16) =
                make_uint4(hi[4*u], hi[4*u+1], hi[4*u+2], hi[4*u+3]);
            *reinterpret_cast<uint4*>(dl + u * 16) =
                make_uint4(lo[4*u], lo[4*u+1], lo[4*u+2], lo[4*u+3]);
        }
    }
    CP_WAIT0();
    __syncthreads();

    float acc[2][8][4];
    int gp = 0;   // global panel counter; active slot = gp & 1

    for (int layer = 0; layer < 4; ++layer) {
        const int K    = (layer == 0) ? HIDDEN : OUT_EMB;
        const int npan = K / 32;
        const int Loff = (layer == 0) ? 0 : 256 * 128 + (layer - 1) * 256 * 256;

        #pragma unroll
        for (int ma = 0; ma < 2; ++ma)
            #pragma unroll
            for (int na = 0; na < 8; ++na)
                #pragma unroll
                for (int i = 0; i < 4; ++i) acc[ma][na][i] = 0.f;

        for (int p = 0; p < npan; ++p, ++gp) {
            // ---- stage next panel (same layer, or next layer's panel 0) ----
            bool staged = true;
            if (p + 1 < npan) {
                const uint32_t dH = sb + SM_B + (uint32_t)((gp + 1) & 1) * BSLOT + stago;
                const int src = Loff + sn * K + (p + 1) * 32 + sc * 16;
                cp16(dH,             g_wh + src);
                cp16(dH + 16,        g_wh + src + 8);
                cp16(dH + BMAT,      g_wl + src);
                cp16(dH + BMAT + 16, g_wl + src + 8);
                CP_COMMIT();
            } else if (layer < 3) {
                const uint32_t dH = sb + SM_B + (uint32_t)((gp + 1) & 1) * BSLOT + stago;
                const int src = 256 * 128 + layer * 256 * 256 + sn * OUT_EMB + sc * 16;
                cp16(dH,             g_wh + src);
                cp16(dH + 16,        g_wh + src + 8);
                cp16(dH + BMAT,      g_wl + src);
                cp16(dH + BMAT + 16, g_wl + src + 8);
                CP_COMMIT();
            } else staged = false;

            // ---- compute panel p (k = p*32 .. +31) ----
            const uint32_t bsH = sb + SM_B + (uint32_t)(gp & 1) * BSLOT;
            #pragma unroll
            for (int ks = 0; ks < 2; ++ks) {
                const int kk = ks * 16;
                uint32_t Ah[2][4], Al[2][4];
                #pragma unroll
                for (int ma = 0; ma < 2; ++ma) {
                    const int row = wm * 32 + ma * 16 + (lid & 7) + ((lid >> 3) & 1) * 8;
                    const int kc  = p * 32 + kk + (lid >> 4) * 8;
                    const uint32_t ad = sb + SM_A_HI + row * 528 + kc * 2;
                    ldsm4(Ah[ma], ad);
                    ldsm4(Al[ma], ad + SM_A_LO);
                }
                #pragma unroll
                for (int bp = 0; bp < 4; ++bp) {
                    const int n  = wn * 64 + bp * 16 + (lid & 7) + (lid >> 4) * 8;
                    const int kb = kk + ((lid >> 3) & 1) * 8;
                    const uint32_t ad = bsH + n * BROW + kb * 2;
                    uint32_t bh[4], bl[4];
                    ldsm4(bh, ad);
                    ldsm4(bl, ad + BMAT);
                    #pragma unroll
                    for (int ma = 0; ma < 2; ++ma) {
                        mma16816(acc[ma][2*bp],     Ah[ma], bh);
                        mma16816(acc[ma][2*bp],     Ah[ma], bl);
                        mma16816(acc[ma][2*bp],     Al[ma], bh);
                        mma16816(acc[ma][2*bp + 1], Ah[ma], bh + 2);
                        mma16816(acc[ma][2*bp + 1], Ah[ma], bl + 2);
                        mma16816(acc[ma][2*bp + 1], Al[ma], bh + 2);
                    }
                }
            }

            if (staged) CP_WAIT0();
            __syncthreads();
        }

        // ---- epilogue ----
        const float* bias_s =
            reinterpret_cast<const float*>(smem + SM_BIAS) + layer * 256;
        if (layer < 3) {
            #pragma unroll
            for (int ma = 0; ma < 2; ++ma)
                #pragma unroll
                for (int na = 0; na < 8; ++na) {
                    const int col = wn * 64 + na * 8 + (lid & 3) * 2;
                    const int r0  = wm * 32 + ma * 16 + (lid >> 2);
                    const float bv0 = bias_s[col], bv1 = bias_s[col + 1];
                    float x0 = acc[ma][na][0] + bv0;
                    float x1 = acc[ma][na][1] + bv1;
                    float x2 = acc[ma][na][2] + bv0;
                    float x3 = acc[ma][na][3] + bv1;
                    if (layer > 0) { x0 = silu(x0); x1 = silu(x1); x2 = silu(x2); x3 = silu(x3); }
                    float h0,l0,h1,l1,h2,l2,h3,l3;
                    bsplit(x0,h0,l0); bsplit(x1,h1,l1);
                    bsplit(x2,h2,l2); bsplit(x3,h3,l3);
                    *reinterpret_cast<uint32_t*>(smem + SM_A_HI + r0*528 + col*2) = packbf2(h0,h1);
                    *reinterpret_cast<uint32_t*>(smem + SM_A_LO + r0*528 + col*2) = packbf2(l0,l1);
                    *reinterpret_cast<uint32_t*>(smem + SM_A_HI + (r0+8)*528 + col*2) = packbf2(h2,h3);
                    *reinterpret_cast<uint32_t*>(smem + SM_A_LO + (r0+8)*528 + col*2) = packbf2(l2,l3);
                }
            __syncthreads();
        } else {
            const float* wo =
                reinterpret_cast<const float*>(smem + SM_BIAS) + 4 * 256;
            float* part = reinterpret_cast<float*>(smem + SM_PART);
            #pragma unroll
            for (int ma = 0; ma < 2; ++ma) {
                float p0 = 0.f, p1 = 0.f;
                #pragma unroll
                for (int na = 0; na < 8; ++na) {
                    const int col = wn * 64 + na * 8 + (lid & 3) * 2;
                    const float bv0 = bias_s[col], bv1 = bias_s[col + 1];
                    const float w0 = wo[col], w1 = wo[col + 1];
                    p0 = fmaf(silu(acc[ma][na][0] + bv0), w0, p0);
                    p0 = fmaf(silu(acc[ma][na][1] + bv1), w1, p0);
                    p1 = fmaf(silu(acc[ma][na][2] + bv0), w0, p1);
                    p1 = fmaf(silu(acc[ma][na][3] + bv1), w1, p1);
                }
                p0 += __shfl_xor_sync(0xffffffffu, p0, 1);
                p0 += __shfl_xor_sync(0xffffffffu, p0, 2);
                p1 += __shfl_xor_sync(0xffffffffu, p1, 1);
                p1 += __shfl_xor_sync(0xffffffffu, p1, 2);
                if ((lid & 3) == 0) {
                    const int r0 = wm * 32 + ma * 16 + (lid >> 2);
                    part[r0 * 4 + wn]       = p0;
                    part[(r0 + 8) * 4 + wn] = p1;
                }
            }
            __syncthreads();
            if (t < 128) {
                const int node = node0 + t;
                if (node < NUM_NODES)
                    out[node] = part[4*t] + part[4*t+1] + part[4*t+2] + part[4*t+3];
            }
        }
    }
}

// ---------------------------------------------------------------------------
extern "C" void kernel_launch(void* const* d_in, const int* in_sizes, int n_in,
                              void* d_out, int out_size)
{
    const float* e2    = (const float*)d_in[0];
    const void*  idx   = d_in[1];
    const float* W_up  = (const float*)d_in[2];
    const float* b_up  = (const float*)d_in[3];
    const float* Ws    = (const float*)d_in[4];
    const float* bs    = (const float*)d_in[5];
    const float* W_out = (const float*)d_in[6];
    float* out = (float*)d_out;

    cudaFuncSetAttribute(mlp_mma_kernel,
                         cudaFuncAttributeMaxDynamicSharedMemorySize, SMEM_BYTES);

    front_kernel<<<Z_BLOCKS + P_BLOCKS, 256>>>((const int*)idx, W_up, Ws);

    const long long scatter_threads = (long long)NUM_EDGES * 32;
    scatter_kernel<<<(int)((scatter_threads + 255) / 256), 256>>>(
        (const float4*)e2, idx);

    const int mlp_blocks = (NUM_NODES + 127) / 128;   // 391
    mlp_mma_kernel<<<mlp_blocks, 512, SMEM_BYTES>>>(b_up, bs, W_out, out);
}